// round 3
// baseline (speedup 1.0000x reference)
#include <cuda_runtime.h>

// BarrierNet fused: 5 -> 128 -> {32,32} -> {2,2} MLP + CBF-QP epilogue.
// 2 rows/thread, outputs split 4-ways across lanes (lane%4 owns 16 outputs).
// Accumulators live in b64 registers (fma.rn.f32x2, no mov pack/unpack in loop).

typedef unsigned long long u64;

__device__ __forceinline__ u64 ffma2u(u64 a, u64 b, u64 c) {
    u64 d;
    asm("fma.rn.f32x2 %0,%1,%2,%3;" : "=l"(d) : "l"(a), "l"(b), "l"(c));
    return d;
}
__device__ __forceinline__ u64 pack2(float v) {
    u64 d;
    asm("mov.b64 %0,{%1,%1};" : "=l"(d) : "f"(v));
    return d;
}
__device__ __forceinline__ float2 unpack2(u64 v) {
    float2 r;
    asm("mov.b64 {%0,%1},%2;" : "=f"(r.x), "=f"(r.y) : "l"(v));
    return r;
}

__global__ __launch_bounds__(256, 2) void barriernet_kernel(
    const float* __restrict__ x,
    const float* __restrict__ mean_, const float* __restrict__ std_,
    const float* __restrict__ w1,  const float* __restrict__ b1,
    const float* __restrict__ w21, const float* __restrict__ b21,
    const float* __restrict__ w22, const float* __restrict__ b22,
    const float* __restrict__ w31, const float* __restrict__ b31,
    const float* __restrict__ w32, const float* __restrict__ b32,
    float2* __restrict__ out, int B)
{
    // s_w2u[k][oi][q] : 16B = weights for outputs {q*16+oi*4 .. +3} at hidden k.
    // q-groups land on distinct bank quads -> conflict-free 4-address LDS.128.
    __shared__ __align__(16) ulonglong2 s_w2u[128][4][4];   // 32 KB
    __shared__ __align__(16) float4 s_w1a[128];             // w1[j][0..3]
    __shared__ float2 s_w1b[128];                           // (w1[j][4], b1[j])
    __shared__ float2 s_b2p[32];                            // bias pairs (concat b21,b22)
    __shared__ float2 s_w3[64];                             // (w3[0][o], w3[1][o]) concat
    __shared__ float  s_b3[4];
    __shared__ float  s_mean[4], s_std[4];

    const int t = threadIdx.x;

    // ---- stage weights ----
    for (int f = t; f < 128 * 16; f += 256) {
        const int k = f >> 4, oi = (f >> 2) & 3, q = f & 3;
        const int o0 = q * 16 + oi * 4;
        float v[4];
#pragma unroll
        for (int j = 0; j < 4; j++) {
            const int o = o0 + j;
            v[j] = (o < 32) ? w21[o * 128 + k] : w22[(o - 32) * 128 + k];
        }
        ulonglong2 u;
        u.x = ((u64)__float_as_uint(v[1]) << 32) | __float_as_uint(v[0]);
        u.y = ((u64)__float_as_uint(v[3]) << 32) | __float_as_uint(v[2]);
        s_w2u[k][oi][q] = u;
    }
    if (t < 128) {
        s_w1a[t] = make_float4(w1[t * 5 + 0], w1[t * 5 + 1], w1[t * 5 + 2], w1[t * 5 + 3]);
        s_w1b[t] = make_float2(w1[t * 5 + 4], b1[t]);
    }
    if (t < 32) {
        s_b2p[t] = (t < 16) ? make_float2(b21[2 * t], b21[2 * t + 1])
                            : make_float2(b22[2 * (t - 16)], b22[2 * (t - 16) + 1]);
    }
    if (t >= 32 && t < 96) {
        const int o = t - 32;
        s_w3[o] = (o < 32) ? make_float2(w31[o], w31[32 + o])
                           : make_float2(w32[o - 32], w32[o]);
    }
    if (t < 4) { s_b3[t] = (t < 2) ? b31[t] : b32[t - 2]; s_mean[t] = mean_[t]; s_std[t] = std_[t]; }
    __syncthreads();

    const int q = t & 3;           // output-quarter owned by this lane
    const int g = t >> 2;          // row group (64 per block)
    const int r0 = blockIdx.x * 128 + g;
    const int r1 = r0 + 64;
    const int r0c = min(r0, B - 1), r1c = min(r1, B - 1);

    float xa[5], xb[5];
#pragma unroll
    for (int i = 0; i < 5; i++) { xa[i] = x[r0c * 5 + i]; xb[i] = x[r1c * 5 + i]; }

    // ---- fused layer1 (streamed) + layer2 partial accumulate (16 outputs) ----
    u64 a0[8], a1[8];
#pragma unroll
    for (int i = 0; i < 8; i++) { a0[i] = 0ull; a1[i] = 0ull; }

#pragma unroll 4
    for (int k = 0; k < 128; k++) {
        const float4 wa = s_w1a[k];
        const float2 wb = s_w1b[k];
        float h0 = fmaf(xa[0], wa.x, fmaf(xa[1], wa.y, fmaf(xa[2], wa.z,
                   fmaf(xa[3], wa.w, fmaf(xa[4], wb.x, wb.y)))));
        float h1 = fmaf(xb[0], wa.x, fmaf(xb[1], wa.y, fmaf(xb[2], wa.z,
                   fmaf(xb[3], wa.w, fmaf(xb[4], wb.x, wb.y)))));
        const u64 H0 = pack2(fmaxf(h0, 0.f));
        const u64 H1 = pack2(fmaxf(h1, 0.f));
#pragma unroll
        for (int oi = 0; oi < 4; oi++) {
            const ulonglong2 w = s_w2u[k][oi][q];
            a0[2 * oi]     = ffma2u(H0, w.x, a0[2 * oi]);
            a0[2 * oi + 1] = ffma2u(H0, w.y, a0[2 * oi + 1]);
            a1[2 * oi]     = ffma2u(H1, w.x, a1[2 * oi]);
            a1[2 * oi + 1] = ffma2u(H1, w.y, a1[2 * oi + 1]);
        }
    }

    // ---- layer-2 bias+relu, layer-3 partials (this lane's 16 outputs) ----
    float2 P[2];  // per-row partial of (u3.x, u3.y) over owned outputs
#pragma unroll
    for (int r = 0; r < 2; r++) {
        const u64* acc = r ? a1 : a0;
        float px0 = 0.f, px1 = 0.f;
#pragma unroll
        for (int o2 = 0; o2 < 8; o2++) {
            const float2 bp = s_b2p[q * 8 + o2];
            const float2 av = unpack2(acc[o2]);
            const float y0 = fmaxf(av.x + bp.x, 0.f);
            const float y1 = fmaxf(av.y + bp.y, 0.f);
            const int o = q * 16 + 2 * o2;
            const float2 w3a = s_w3[o];
            const float2 w3b = s_w3[o + 1];
            px0 = fmaf(y0, w3a.x, fmaf(y1, w3b.x, px0));
            px1 = fmaf(y0, w3a.y, fmaf(y1, w3b.y, px1));
        }
        P[r] = make_float2(px0, px1);
    }

    // ---- combine across the 4 lanes of the group ----
    // q in {0,1} holds u3a partials; q in {2,3} holds u3b partials.
    const unsigned FULL = 0xFFFFFFFFu;
    float2 Q[2];
#pragma unroll
    for (int r = 0; r < 2; r++) {
        P[r].x += __shfl_xor_sync(FULL, P[r].x, 1);
        P[r].y += __shfl_xor_sync(FULL, P[r].y, 1);
        Q[r].x = __shfl_xor_sync(FULL, P[r].x, 2);
        Q[r].y = __shfl_xor_sync(FULL, P[r].y, 2);
    }
    // lane q==0 -> row r0, lane q==1 -> row r1 (P holds u3a, Q holds u3b there)
    if (q < 2) {
        const int r   = q;
        const int row = r ? r1 : r0;
        if (row < B) {
            const float2 u3a = P[r];
            const float2 u3b = Q[r];
            const float* xi = r ? xb : xa;

            const float px = xi[0] * s_std[0] + s_mean[0];
            const float py = xi[1] * s_std[1] + s_mean[1];
            const float th = xi[2] * s_std[2] + s_mean[2];
            const float v  = xi[3] * s_std[3] + s_mean[3];
            float s, c;
            sincosf(th, &s, &c);
            const float dx = px - 40.0f;
            const float dy = py - 15.0f;
            const float barrier = dx * dx + dy * dy - 36.0f;
            const float bdot    = 2.0f * dx * v * c + 2.0f * dy * v * s;
            const float Lf2b    = 2.0f * v * v;
            const float g1 = -(-2.0f * dx * v * s + 2.0f * dy * v * c);
            const float g2 = -(2.0f * dx * c + 2.0f * dy * s);

            const float u0x = -(u3a.x + s_b3[0]);
            const float u0y = -(u3a.y + s_b3[1]);
            const float z1 = u3b.x + s_b3[2];
            const float z2 = u3b.y + s_b3[3];
            const float x32_0 = 4.0f / (1.0f + expf(-z1));
            const float x32_1 = 4.0f / (1.0f + expf(-z2));

            const float hq   = Lf2b + (x32_0 + x32_1) * bdot + x32_0 * x32_1 * barrier;
            const float viol = g1 * u0x + g2 * u0y - hq;
            const float gg   = g1 * g1 + g2 * g2;
            const float lam  = fmaxf(viol, 0.f) / (gg + 1e-12f);

            out[row] = make_float2(u0x - lam * g1, u0y - lam * g2);
        }
    }
}

extern "C" void kernel_launch(void* const* d_in, const int* in_sizes, int n_in,
                              void* d_out, int out_size) {
    const float* x     = (const float*)d_in[0];
    const float* mean_ = (const float*)d_in[2];
    const float* std_  = (const float*)d_in[3];
    const float* w1    = (const float*)d_in[4];
    const float* b1    = (const float*)d_in[5];
    const float* w21   = (const float*)d_in[6];
    const float* b21   = (const float*)d_in[7];
    const float* w22   = (const float*)d_in[8];
    const float* b22   = (const float*)d_in[9];
    const float* w31   = (const float*)d_in[10];
    const float* b31   = (const float*)d_in[11];
    const float* w32   = (const float*)d_in[12];
    const float* b32   = (const float*)d_in[13];

    const int B = in_sizes[0] / 5;
    const int blocks = (B + 127) / 128;   // 128 rows per 256-thread block
    barriernet_kernel<<<blocks, 256>>>(x, mean_, std_, w1, b1, w21, b21,
                                       w22, b22, w31, b31, w32, b32,
                                       (float2*)d_out, B);
}

// round 6
// speedup vs baseline: 2.7602x; 2.7602x over previous
#include <cuda_runtime.h>
#include <cuda_bf16.h>
#include <cstdint>

// BarrierNet via mma.sync (HMMA) split-precision bf16, sm_80-compatible PTX.
// Layer1 (5->128, bias folded as k=5 input) as m16n8k8 MMA; its D fragments
// are relu'd, split hi/lo bf16, and repacked IN REGISTERS as the A fragments
// of layer2 (128->64) m16n8k16 MMA. 3-term split => ~1e-5 accuracy.
// Each warp: 32 rows x 64 outputs. CTA: 256 rows.

__device__ __forceinline__ uint32_t smem_u32(const void* p) {
    uint32_t a;
    asm("{ .reg .u64 t; cvta.to.shared.u64 t, %1; cvt.u32.u64 %0, t; }" : "=r"(a) : "l"(p));
    return a;
}
__device__ __forceinline__ void ldmx4(uint32_t& r0, uint32_t& r1, uint32_t& r2, uint32_t& r3, uint32_t a) {
    asm volatile("ldmatrix.sync.aligned.m8n8.x4.shared.b16 {%0,%1,%2,%3}, [%4];"
                 : "=r"(r0), "=r"(r1), "=r"(r2), "=r"(r3) : "r"(a));
}
__device__ __forceinline__ void ldmx2(uint32_t& r0, uint32_t& r1, uint32_t a) {
    asm volatile("ldmatrix.sync.aligned.m8n8.x2.shared.b16 {%0,%1}, [%2];"
                 : "=r"(r0), "=r"(r1) : "r"(a));
}
__device__ __forceinline__ void mma16(float* c, const uint32_t* a, const uint32_t* b) {
    asm volatile("mma.sync.aligned.m16n8k16.row.col.f32.bf16.bf16.f32 "
                 "{%0,%1,%2,%3}, {%4,%5,%6,%7}, {%8,%9}, {%0,%1,%2,%3};"
                 : "+f"(c[0]), "+f"(c[1]), "+f"(c[2]), "+f"(c[3])
                 : "r"(a[0]), "r"(a[1]), "r"(a[2]), "r"(a[3]), "r"(b[0]), "r"(b[1]));
}
__device__ __forceinline__ void mma8(float* c, const uint32_t* a, uint32_t b) {
    asm volatile("mma.sync.aligned.m16n8k8.row.col.f32.bf16.bf16.f32 "
                 "{%0,%1,%2,%3}, {%4,%5}, {%6}, {%0,%1,%2,%3};"
                 : "+f"(c[0]), "+f"(c[1]), "+f"(c[2]), "+f"(c[3])
                 : "r"(a[0]), "r"(a[1]), "r"(b));
}
// pack two f32 -> bf16x2: first asm operand -> HIGH half
__device__ __forceinline__ uint32_t cvt2(float hi, float lo) {
    uint32_t r;
    asm("cvt.rn.bf16x2.f32 %0, %1, %2;" : "=r"(r) : "f"(hi), "f"(lo));
    return r;
}
__device__ __forceinline__ float lo_f(uint32_t p) { return __uint_as_float(p << 16); }
__device__ __forceinline__ float hi_f(uint32_t p) { return __uint_as_float(p & 0xFFFF0000u); }

static constexpr int TILE_M = 256;

__global__ __launch_bounds__(256) void barriernet_mma_kernel(
    const float* __restrict__ x,
    const float* __restrict__ mean_, const float* __restrict__ std_,
    const float* __restrict__ w1,  const float* __restrict__ b1,
    const float* __restrict__ w21, const float* __restrict__ b21,
    const float* __restrict__ w22, const float* __restrict__ b22,
    const float* __restrict__ w31, const float* __restrict__ b31,
    const float* __restrict__ w32, const float* __restrict__ b32,
    float2* __restrict__ out, int B)
{
    __shared__ __align__(16) float s_x[256][8];       // 8KB: x0..x4, 1, 0, 0
    __shared__ __align__(16) uint4 s_w1h[128], s_w1l[128];   // [n][k8] bf16x2x4
    __shared__ __align__(16) uint4 s_w2h[64][16], s_w2l[64][16]; // [n][chunk] swizzled
    __shared__ __align__(16) float4 s_ep[64];         // (b2, w3row0, w3row1, 0)
    __shared__ float s_b3[4], s_ms[8];

    const int t = threadIdx.x;
    const int tile = blockIdx.x * TILE_M;

    // ---- stage x (padded, bias column at k=5) ----
    for (int i = t; i < 256 * 8; i += 256) {
        const int r = i >> 3, k = i & 7;
        float v;
        if (k < 5) { const int gr = min(tile + r, B - 1); v = x[(size_t)gr * 5 + k]; }
        else v = (k == 5) ? 1.0f : 0.0f;
        s_x[r][k] = v;
    }
    // ---- stage W1 rows [n][k=8]: w1[n][0..4], b1[n], 0, 0 ; hi/lo split ----
    if (t < 128) {
        float v[8];
#pragma unroll
        for (int i = 0; i < 5; i++) v[i] = w1[t * 5 + i];
        v[5] = b1[t]; v[6] = 0.f; v[7] = 0.f;
        uint4 h, l;
        h.x = cvt2(v[1], v[0]); l.x = cvt2(v[1] - hi_f(h.x), v[0] - lo_f(h.x));
        h.y = cvt2(v[3], v[2]); l.y = cvt2(v[3] - hi_f(h.y), v[2] - lo_f(h.y));
        h.z = cvt2(v[5], v[4]); l.z = cvt2(v[5] - hi_f(h.z), v[4] - lo_f(h.z));
        h.w = 0u;               l.w = 0u;
        s_w1h[t] = h; s_w1l[t] = l;
    }
    // ---- stage W2 [n=64][k=128] hi/lo, 16B-chunk XOR swizzle ----
    for (int i = t; i < 64 * 16; i += 256) {
        const int n = i >> 4, c = i & 15;
        const float* src = (n < 32) ? (w21 + n * 128 + c * 8)
                                    : (w22 + (n - 32) * 128 + c * 8);
        uint4 h, l;
        h.x = cvt2(src[1], src[0]); l.x = cvt2(src[1] - hi_f(h.x), src[0] - lo_f(h.x));
        h.y = cvt2(src[3], src[2]); l.y = cvt2(src[3] - hi_f(h.y), src[2] - lo_f(h.y));
        h.z = cvt2(src[5], src[4]); l.z = cvt2(src[5] - hi_f(h.z), src[4] - lo_f(h.z));
        h.w = cvt2(src[7], src[6]); l.w = cvt2(src[7] - hi_f(h.w), src[6] - lo_f(h.w));
        const int cs = c ^ (n & 7);
        s_w2h[n][cs] = h; s_w2l[n][cs] = l;
    }
    if (t < 64) {
        s_ep[t] = (t < 32) ? make_float4(b21[t], w31[t], w31[32 + t], 0.f)
                           : make_float4(b22[t - 32], w32[t - 32], w32[t], 0.f);
    }
    if (t < 4) s_b3[t] = (t < 2) ? b31[t] : b32[t - 2];
    if (t >= 8 && t < 16) s_ms[t - 8] = (t < 12) ? mean_[t - 8] : std_[t - 12];
    __syncthreads();

    const int wid = t >> 5, lane = t & 31;
    const int g = lane >> 2, tig = lane & 3;
    const int rb = wid * 32;

    // ---- x fragments (A of layer1, m16k8): a0=(row g,k01), a1=(row g+8,k01) ----
    uint32_t xh[2][2], xl[2][2];
#pragma unroll
    for (int s = 0; s < 2; s++) {
        const float2 v0 = *(const float2*)&s_x[rb + s * 16 + g][tig * 2];
        const float2 v1 = *(const float2*)&s_x[rb + s * 16 + g + 8][tig * 2];
        xh[s][0] = cvt2(v0.y, v0.x);
        xl[s][0] = cvt2(v0.y - hi_f(xh[s][0]), v0.x - lo_f(xh[s][0]));
        xh[s][1] = cvt2(v1.y, v1.x);
        xl[s][1] = cvt2(v1.y - hi_f(xh[s][1]), v1.x - lo_f(xh[s][1]));
    }

    float acc[2][8][4];
#pragma unroll
    for (int s = 0; s < 2; s++)
#pragma unroll
        for (int nf = 0; nf < 8; nf++)
#pragma unroll
            for (int q = 0; q < 4; q++) acc[s][nf][q] = 0.f;

    const uint32_t w1h_base = smem_u32(s_w1h), w1l_base = smem_u32(s_w1l);
    const uint32_t w2h_base = smem_u32(s_w2h), w2l_base = smem_u32(s_w2l);
    const uint32_t nrow  = (uint32_t)((lane & 7) + ((lane & 16) >> 1));
    const uint32_t klane = (uint32_t)((lane >> 3) & 1);

#pragma unroll
    for (int j = 0; j < 8; j++) {
        // ---- layer 1 chunk j: h[rows][16j..16j+15] ----
        uint32_t wh[2], wl[2];
        {
            const uint32_t a = (uint32_t)((j * 16 + (lane & 15)) * 16);
            ldmx2(wh[0], wh[1], w1h_base + a);
            ldmx2(wl[0], wl[1], w1l_base + a);
        }
        uint32_t Ah[2][4], Al[2][4];
#pragma unroll
        for (int s = 0; s < 2; s++) {
            float d[2][4];
#pragma unroll
            for (int nf = 0; nf < 2; nf++) {
                d[nf][0] = d[nf][1] = d[nf][2] = d[nf][3] = 0.f;
                mma8(d[nf], xh[s], wh[nf]);
                mma8(d[nf], xl[s], wh[nf]);
                mma8(d[nf], xh[s], wl[nf]);
#pragma unroll
                for (int q = 0; q < 4; q++) d[nf][q] = fmaxf(d[nf][q], 0.f);
            }
            // D(layer1) -> A(layer2) fragment identity
            Ah[s][0] = cvt2(d[0][1], d[0][0]);
            Al[s][0] = cvt2(d[0][1] - hi_f(Ah[s][0]), d[0][0] - lo_f(Ah[s][0]));
            Ah[s][1] = cvt2(d[0][3], d[0][2]);
            Al[s][1] = cvt2(d[0][3] - hi_f(Ah[s][1]), d[0][2] - lo_f(Ah[s][1]));
            Ah[s][2] = cvt2(d[1][1], d[1][0]);
            Al[s][2] = cvt2(d[1][1] - hi_f(Ah[s][2]), d[1][0] - lo_f(Ah[s][2]));
            Ah[s][3] = cvt2(d[1][3], d[1][2]);
            Al[s][3] = cvt2(d[1][3] - hi_f(Ah[s][3]), d[1][2] - lo_f(Ah[s][3]));
        }

        // ---- layer 2: B frags for k-chunk j (all 64 n), then 3-term MMA ----
        uint32_t bh[8][2], bl[8][2];
#pragma unroll
        for (int p = 0; p < 4; p++) {
            const uint32_t n  = nrow + (uint32_t)(p * 16);
            const uint32_t a  = (n << 8) + ((((uint32_t)(2 * j) + klane) ^ (n & 7)) << 4);
            ldmx4(bh[2 * p][0], bh[2 * p][1], bh[2 * p + 1][0], bh[2 * p + 1][1], w2h_base + a);
            ldmx4(bl[2 * p][0], bl[2 * p][1], bl[2 * p + 1][0], bl[2 * p + 1][1], w2l_base + a);
        }
#pragma unroll
        for (int s = 0; s < 2; s++)
#pragma unroll
            for (int nf = 0; nf < 8; nf++) {
                mma16(acc[s][nf], Ah[s], bh[nf]);
                mma16(acc[s][nf], Al[s], bh[nf]);
                mma16(acc[s][nf], Ah[s], bl[nf]);
            }
    }

    // ---- epilogue: bias+relu, layer-3 dots, quad reduction, QP ----
    float P[4][4];
#pragma unroll
    for (int s = 0; s < 2; s++)
#pragma unroll
        for (int o = 0; o < 2; o++) {
            float pax = 0.f, pay = 0.f, pbx = 0.f, pby = 0.f;
#pragma unroll
            for (int nf = 0; nf < 8; nf++) {
                const int n0 = nf * 8 + tig * 2;
                const float4 e0 = s_ep[n0];
                const float4 e1 = s_ep[n0 + 1];
                const float y0 = fmaxf(acc[s][nf][o * 2 + 0] + e0.x, 0.f);
                const float y1 = fmaxf(acc[s][nf][o * 2 + 1] + e1.x, 0.f);
                if (nf < 4) {
                    pax = fmaf(y0, e0.y, fmaf(y1, e1.y, pax));
                    pay = fmaf(y0, e0.z, fmaf(y1, e1.z, pay));
                } else {
                    pbx = fmaf(y0, e0.y, fmaf(y1, e1.y, pbx));
                    pby = fmaf(y0, e0.z, fmaf(y1, e1.z, pby));
                }
            }
            P[s * 2 + o][0] = pax; P[s * 2 + o][1] = pay;
            P[s * 2 + o][2] = pbx; P[s * 2 + o][3] = pby;
        }
#pragma unroll
    for (int sl = 0; sl < 4; sl++)
#pragma unroll
        for (int c = 0; c < 4; c++) {
            P[sl][c] += __shfl_xor_sync(0xFFFFFFFFu, P[sl][c], 1);
            P[sl][c] += __shfl_xor_sync(0xFFFFFFFFu, P[sl][c], 2);
        }

    // lane tig handles slot tig (row = rb + (tig>>1)*16 + (tig&1)*8 + g)
    float uax, uay, ubx, uby;
    if      (tig == 0) { uax = P[0][0]; uay = P[0][1]; ubx = P[0][2]; uby = P[0][3]; }
    else if (tig == 1) { uax = P[1][0]; uay = P[1][1]; ubx = P[1][2]; uby = P[1][3]; }
    else if (tig == 2) { uax = P[2][0]; uay = P[2][1]; ubx = P[2][2]; uby = P[2][3]; }
    else               { uax = P[3][0]; uay = P[3][1]; ubx = P[3][2]; uby = P[3][3]; }

    const int rl = rb + (tig >> 1) * 16 + (tig & 1) * 8 + g;
    const int gr = tile + rl;
    if (gr < B) {
        const float px = s_x[rl][0] * s_ms[4] + s_ms[0];
        const float py = s_x[rl][1] * s_ms[5] + s_ms[1];
        const float th = s_x[rl][2] * s_ms[6] + s_ms[2];
        const float v  = s_x[rl][3] * s_ms[7] + s_ms[3];
        float s, c;
        sincosf(th, &s, &c);
        const float dx = px - 40.0f, dy = py - 15.0f;
        const float barrier = dx * dx + dy * dy - 36.0f;
        const float bdot = 2.0f * dx * v * c + 2.0f * dy * v * s;
        const float Lf2b = 2.0f * v * v;
        const float g1 = -(-2.0f * dx * v * s + 2.0f * dy * v * c);
        const float g2 = -(2.0f * dx * c + 2.0f * dy * s);

        const float u0x = -(uax + s_b3[0]);
        const float u0y = -(uay + s_b3[1]);
        const float z1 = ubx + s_b3[2];
        const float z2 = uby + s_b3[3];
        const float x32_0 = 4.0f / (1.0f + expf(-z1));
        const float x32_1 = 4.0f / (1.0f + expf(-z2));

        const float hq   = Lf2b + (x32_0 + x32_1) * bdot + x32_0 * x32_1 * barrier;
        const float viol = g1 * u0x + g2 * u0y - hq;
        const float gg   = g1 * g1 + g2 * g2;
        const float lam  = fmaxf(viol, 0.f) / (gg + 1e-12f);

        out[gr] = make_float2(u0x - lam * g1, u0y - lam * g2);
    }
}

extern "C" void kernel_launch(void* const* d_in, const int* in_sizes, int n_in,
                              void* d_out, int out_size) {
    const float* x     = (const float*)d_in[0];
    const float* mean_ = (const float*)d_in[2];
    const float* std_  = (const float*)d_in[3];
    const float* w1    = (const float*)d_in[4];
    const float* b1    = (const float*)d_in[5];
    const float* w21   = (const float*)d_in[6];
    const float* b21   = (const float*)d_in[7];
    const float* w22   = (const float*)d_in[8];
    const float* b22   = (const float*)d_in[9];
    const float* w31   = (const float*)d_in[10];
    const float* b31   = (const float*)d_in[11];
    const float* w32   = (const float*)d_in[12];
    const float* b32   = (const float*)d_in[13];

    const int B = in_sizes[0] / 5;
    const int blocks = (B + TILE_M - 1) / TILE_M;
    barriernet_mma_kernel<<<blocks, 256>>>(x, mean_, std_, w1, b1, w21, b21,
                                           w22, b22, w31, b31, w32, b32,
                                           (float2*)d_out, B);
}

// round 8
// speedup vs baseline: 4.0985x; 1.4848x over previous
#include <cuda_runtime.h>
#include <cuda_bf16.h>
#include <cstdint>

// BarrierNet via mma.sync (HMMA) split-precision bf16, sm_80-compatible PTX.
// Layer1 (5->128, bias folded as k=5 input) as m16n8k8 MMA; its D fragments
// are relu'd, split hi/lo bf16, and repacked IN REGISTERS as the A fragments
// of layer2 (128->64) m16n8k16 MMA. 3-term split => ~1e-5 accuracy.
// Each warp: 32 rows x 64 outputs. CTA: 256 rows. 2 CTAs/SM (<=128 regs).

__device__ __forceinline__ uint32_t smem_u32(const void* p) {
    uint32_t a;
    asm("{ .reg .u64 t; cvta.to.shared.u64 t, %1; cvt.u32.u64 %0, t; }" : "=r"(a) : "l"(p));
    return a;
}
__device__ __forceinline__ void ldmx4(uint32_t& r0, uint32_t& r1, uint32_t& r2, uint32_t& r3, uint32_t a) {
    asm volatile("ldmatrix.sync.aligned.m8n8.x4.shared.b16 {%0,%1,%2,%3}, [%4];"
                 : "=r"(r0), "=r"(r1), "=r"(r2), "=r"(r3) : "r"(a));
}
__device__ __forceinline__ void ldmx2(uint32_t& r0, uint32_t& r1, uint32_t a) {
    asm volatile("ldmatrix.sync.aligned.m8n8.x2.shared.b16 {%0,%1}, [%2];"
                 : "=r"(r0), "=r"(r1) : "r"(a));
}
__device__ __forceinline__ void mma16(float* c, const uint32_t* a, const uint32_t* b) {
    asm volatile("mma.sync.aligned.m16n8k16.row.col.f32.bf16.bf16.f32 "
                 "{%0,%1,%2,%3}, {%4,%5,%6,%7}, {%8,%9}, {%0,%1,%2,%3};"
                 : "+f"(c[0]), "+f"(c[1]), "+f"(c[2]), "+f"(c[3])
                 : "r"(a[0]), "r"(a[1]), "r"(a[2]), "r"(a[3]), "r"(b[0]), "r"(b[1]));
}
__device__ __forceinline__ void mma8(float* c, const uint32_t* a, uint32_t b) {
    asm volatile("mma.sync.aligned.m16n8k8.row.col.f32.bf16.bf16.f32 "
                 "{%0,%1,%2,%3}, {%4,%5}, {%6}, {%0,%1,%2,%3};"
                 : "+f"(c[0]), "+f"(c[1]), "+f"(c[2]), "+f"(c[3])
                 : "r"(a[0]), "r"(a[1]), "r"(b));
}
// pack two f32 -> bf16x2: first asm operand -> HIGH half
__device__ __forceinline__ uint32_t cvt2(float hi, float lo) {
    uint32_t r;
    asm("cvt.rn.bf16x2.f32 %0, %1, %2;" : "=r"(r) : "f"(hi), "f"(lo));
    return r;
}
__device__ __forceinline__ float lo_f(uint32_t p) { return __uint_as_float(p << 16); }
__device__ __forceinline__ float hi_f(uint32_t p) { return __uint_as_float(p & 0xFFFF0000u); }

static constexpr int TILE_M = 256;

__global__ __launch_bounds__(256, 2) void barriernet_mma_kernel(
    const float* __restrict__ x,
    const float* __restrict__ mean_, const float* __restrict__ std_,
    const float* __restrict__ w1,  const float* __restrict__ b1,
    const float* __restrict__ w21, const float* __restrict__ b21,
    const float* __restrict__ w22, const float* __restrict__ b22,
    const float* __restrict__ w31, const float* __restrict__ b31,
    const float* __restrict__ w32, const float* __restrict__ b32,
    float2* __restrict__ out, int B)
{
    __shared__ __align__(16) float s_x[256][8];       // 8KB: x0..x4, 1, 0, 0
    __shared__ __align__(16) uint4 s_w1h[128], s_w1l[128];   // [n][k8] bf16x2x4
    __shared__ __align__(16) uint4 s_w2h[64][16], s_w2l[64][16]; // [n][chunk] swizzled
    __shared__ __align__(16) float4 s_ep[64];         // (b2, w3row0, w3row1, 0)
    __shared__ float s_b3[4], s_ms[8];

    const int t = threadIdx.x;
    const int tile = blockIdx.x * TILE_M;

    // ---- stage x (padded, bias column at k=5) ----
    for (int i = t; i < 256 * 8; i += 256) {
        const int r = i >> 3, k = i & 7;
        float v;
        if (k < 5) { const int gr = min(tile + r, B - 1); v = x[(size_t)gr * 5 + k]; }
        else v = (k == 5) ? 1.0f : 0.0f;
        s_x[r][k] = v;
    }
    // ---- stage W1 rows [n][k=8]: w1[n][0..4], b1[n], 0, 0 ; hi/lo split ----
    if (t < 128) {
        float v[8];
#pragma unroll
        for (int i = 0; i < 5; i++) v[i] = w1[t * 5 + i];
        v[5] = b1[t]; v[6] = 0.f; v[7] = 0.f;
        uint4 h, l;
        h.x = cvt2(v[1], v[0]); l.x = cvt2(v[1] - hi_f(h.x), v[0] - lo_f(h.x));
        h.y = cvt2(v[3], v[2]); l.y = cvt2(v[3] - hi_f(h.y), v[2] - lo_f(h.y));
        h.z = cvt2(v[5], v[4]); l.z = cvt2(v[5] - hi_f(h.z), v[4] - lo_f(h.z));
        h.w = 0u;               l.w = 0u;
        s_w1h[t] = h; s_w1l[t] = l;
    }
    // ---- stage W2 [n=64][k=128] hi/lo, 16B-chunk XOR swizzle ----
    for (int i = t; i < 64 * 16; i += 256) {
        const int n = i >> 4, c = i & 15;
        const float* src = (n < 32) ? (w21 + n * 128 + c * 8)
                                    : (w22 + (n - 32) * 128 + c * 8);
        uint4 h, l;
        h.x = cvt2(src[1], src[0]); l.x = cvt2(src[1] - hi_f(h.x), src[0] - lo_f(h.x));
        h.y = cvt2(src[3], src[2]); l.y = cvt2(src[3] - hi_f(h.y), src[2] - lo_f(h.y));
        h.z = cvt2(src[5], src[4]); l.z = cvt2(src[5] - hi_f(h.z), src[4] - lo_f(h.z));
        h.w = cvt2(src[7], src[6]); l.w = cvt2(src[7] - hi_f(h.w), src[6] - lo_f(h.w));
        const int cs = c ^ (n & 7);
        s_w2h[n][cs] = h; s_w2l[n][cs] = l;
    }
    if (t < 64) {
        s_ep[t] = (t < 32) ? make_float4(b21[t], w31[t], w31[32 + t], 0.f)
                           : make_float4(b22[t - 32], w32[t - 32], w32[t], 0.f);
    }
    if (t < 4) s_b3[t] = (t < 2) ? b31[t] : b32[t - 2];
    if (t >= 8 && t < 16) s_ms[t - 8] = (t < 12) ? mean_[t - 8] : std_[t - 12];
    __syncthreads();

    const int wid = t >> 5, lane = t & 31;
    const int g = lane >> 2, tig = lane & 3;
    const int rb = wid * 32;

    // ---- x fragments (A of layer1, m16k8): a0=(row g,k01), a1=(row g+8,k01) ----
    uint32_t xh[2][2], xl[2][2];
#pragma unroll
    for (int s = 0; s < 2; s++) {
        const float2 v0 = *(const float2*)&s_x[rb + s * 16 + g][tig * 2];
        const float2 v1 = *(const float2*)&s_x[rb + s * 16 + g + 8][tig * 2];
        xh[s][0] = cvt2(v0.y, v0.x);
        xl[s][0] = cvt2(v0.y - hi_f(xh[s][0]), v0.x - lo_f(xh[s][0]));
        xh[s][1] = cvt2(v1.y, v1.x);
        xl[s][1] = cvt2(v1.y - hi_f(xh[s][1]), v1.x - lo_f(xh[s][1]));
    }

    float acc[2][8][4];
#pragma unroll
    for (int s = 0; s < 2; s++)
#pragma unroll
        for (int nf = 0; nf < 8; nf++)
#pragma unroll
            for (int q = 0; q < 4; q++) acc[s][nf][q] = 0.f;

    const uint32_t w1h_base = smem_u32(s_w1h), w1l_base = smem_u32(s_w1l);
    const uint32_t w2h_base = smem_u32(s_w2h), w2l_base = smem_u32(s_w2l);
    const uint32_t nrow  = (uint32_t)((lane & 7) + ((lane & 16) >> 1));
    const uint32_t klane = (uint32_t)((lane >> 3) & 1);

#pragma unroll
    for (int j = 0; j < 8; j++) {
        // ---- layer 1 chunk j: h[rows][16j..16j+15] ----
        uint32_t wh[2], wl[2];
        {
            const uint32_t a = (uint32_t)((j * 16 + (lane & 15)) * 16);
            ldmx2(wh[0], wh[1], w1h_base + a);
            ldmx2(wl[0], wl[1], w1l_base + a);
        }
        uint32_t Ah[2][4], Al[2][4];
#pragma unroll
        for (int s = 0; s < 2; s++) {
            float d[2][4];
#pragma unroll
            for (int nf = 0; nf < 2; nf++) {
                d[nf][0] = d[nf][1] = d[nf][2] = d[nf][3] = 0.f;
                mma8(d[nf], xh[s], wh[nf]);
                mma8(d[nf], xl[s], wh[nf]);
                mma8(d[nf], xh[s], wl[nf]);
#pragma unroll
                for (int q = 0; q < 4; q++) d[nf][q] = fmaxf(d[nf][q], 0.f);
            }
            // D(layer1) -> A(layer2) fragment identity
            Ah[s][0] = cvt2(d[0][1], d[0][0]);
            Al[s][0] = cvt2(d[0][1] - hi_f(Ah[s][0]), d[0][0] - lo_f(Ah[s][0]));
            Ah[s][1] = cvt2(d[0][3], d[0][2]);
            Al[s][1] = cvt2(d[0][3] - hi_f(Ah[s][1]), d[0][2] - lo_f(Ah[s][1]));
            Ah[s][2] = cvt2(d[1][1], d[1][0]);
            Al[s][2] = cvt2(d[1][1] - hi_f(Ah[s][2]), d[1][0] - lo_f(Ah[s][2]));
            Ah[s][3] = cvt2(d[1][3], d[1][2]);
            Al[s][3] = cvt2(d[1][3] - hi_f(Ah[s][3]), d[1][2] - lo_f(Ah[s][3]));
        }

        // ---- layer 2: per n-pair, load B frags then immediately consume ----
        // (short live-range: 8 B-regs live at a time, fits 128-reg budget)
#pragma unroll
        for (int p = 0; p < 4; p++) {
            uint32_t bh0[2], bh1[2], bl0[2], bl1[2];
            const uint32_t n  = nrow + (uint32_t)(p * 16);
            const uint32_t a  = (n << 8) + ((((uint32_t)(2 * j) + klane) ^ (n & 7)) << 4);
            ldmx4(bh0[0], bh0[1], bh1[0], bh1[1], w2h_base + a);
            ldmx4(bl0[0], bl0[1], bl1[0], bl1[1], w2l_base + a);
#pragma unroll
            for (int s = 0; s < 2; s++) {
                mma16(acc[s][2 * p],     Ah[s], bh0);
                mma16(acc[s][2 * p + 1], Ah[s], bh1);
                mma16(acc[s][2 * p],     Al[s], bh0);
                mma16(acc[s][2 * p + 1], Al[s], bh1);
                mma16(acc[s][2 * p],     Ah[s], bl0);
                mma16(acc[s][2 * p + 1], Ah[s], bl1);
            }
        }
    }

    // ---- epilogue: bias+relu, layer-3 dots, quad reduction, QP ----
    float P[4][4];
#pragma unroll
    for (int s = 0; s < 2; s++)
#pragma unroll
        for (int o = 0; o < 2; o++) {
            float pax = 0.f, pay = 0.f, pbx = 0.f, pby = 0.f;
#pragma unroll
            for (int nf = 0; nf < 8; nf++) {
                const int n0 = nf * 8 + tig * 2;
                const float4 e0 = s_ep[n0];
                const float4 e1 = s_ep[n0 + 1];
                const float y0 = fmaxf(acc[s][nf][o * 2 + 0] + e0.x, 0.f);
                const float y1 = fmaxf(acc[s][nf][o * 2 + 1] + e1.x, 0.f);
                if (nf < 4) {
                    pax = fmaf(y0, e0.y, fmaf(y1, e1.y, pax));
                    pay = fmaf(y0, e0.z, fmaf(y1, e1.z, pay));
                } else {
                    pbx = fmaf(y0, e0.y, fmaf(y1, e1.y, pbx));
                    pby = fmaf(y0, e0.z, fmaf(y1, e1.z, pby));
                }
            }
            P[s * 2 + o][0] = pax; P[s * 2 + o][1] = pay;
            P[s * 2 + o][2] = pbx; P[s * 2 + o][3] = pby;
        }
#pragma unroll
    for (int sl = 0; sl < 4; sl++)
#pragma unroll
        for (int c = 0; c < 4; c++) {
            P[sl][c] += __shfl_xor_sync(0xFFFFFFFFu, P[sl][c], 1);
            P[sl][c] += __shfl_xor_sync(0xFFFFFFFFu, P[sl][c], 2);
        }

    // lane tig handles slot tig (row = rb + (tig>>1)*16 + (tig&1)*8 + g)
    float uax, uay, ubx, uby;
    if      (tig == 0) { uax = P[0][0]; uay = P[0][1]; ubx = P[0][2]; uby = P[0][3]; }
    else if (tig == 1) { uax = P[1][0]; uay = P[1][1]; ubx = P[1][2]; uby = P[1][3]; }
    else if (tig == 2) { uax = P[2][0]; uay = P[2][1]; ubx = P[2][2]; uby = P[2][3]; }
    else               { uax = P[3][0]; uay = P[3][1]; ubx = P[3][2]; uby = P[3][3]; }

    const int rl = rb + (tig >> 1) * 16 + (tig & 1) * 8 + g;
    const int gr = tile + rl;
    if (gr < B) {
        const float px = s_x[rl][0] * s_ms[4] + s_ms[0];
        const float py = s_x[rl][1] * s_ms[5] + s_ms[1];
        const float th = s_x[rl][2] * s_ms[6] + s_ms[2];
        const float v  = s_x[rl][3] * s_ms[7] + s_ms[3];
        float s, c;
        sincosf(th, &s, &c);
        const float dx = px - 40.0f, dy = py - 15.0f;
        const float barrier = dx * dx + dy * dy - 36.0f;
        const float bdot = 2.0f * dx * v * c + 2.0f * dy * v * s;
        const float Lf2b = 2.0f * v * v;
        const float g1 = -(-2.0f * dx * v * s + 2.0f * dy * v * c);
        const float g2 = -(2.0f * dx * c + 2.0f * dy * s);

        const float u0x = -(uax + s_b3[0]);
        const float u0y = -(uay + s_b3[1]);
        const float z1 = ubx + s_b3[2];
        const float z2 = uby + s_b3[3];
        const float x32_0 = 4.0f / (1.0f + expf(-z1));
        const float x32_1 = 4.0f / (1.0f + expf(-z2));

        const float hq   = Lf2b + (x32_0 + x32_1) * bdot + x32_0 * x32_1 * barrier;
        const float viol = g1 * u0x + g2 * u0y - hq;
        const float gg   = g1 * g1 + g2 * g2;
        const float lam  = fmaxf(viol, 0.f) / (gg + 1e-12f);

        out[gr] = make_float2(u0x - lam * g1, u0y - lam * g2);
    }
}

extern "C" void kernel_launch(void* const* d_in, const int* in_sizes, int n_in,
                              void* d_out, int out_size) {
    const float* x     = (const float*)d_in[0];
    const float* mean_ = (const float*)d_in[2];
    const float* std_  = (const float*)d_in[3];
    const float* w1    = (const float*)d_in[4];
    const float* b1    = (const float*)d_in[5];
    const float* w21   = (const float*)d_in[6];
    const float* b21   = (const float*)d_in[7];
    const float* w22   = (const float*)d_in[8];
    const float* b22   = (const float*)d_in[9];
    const float* w31   = (const float*)d_in[10];
    const float* b31   = (const float*)d_in[11];
    const float* w32   = (const float*)d_in[12];
    const float* b32   = (const float*)d_in[13];

    const int B = in_sizes[0] / 5;
    const int blocks = (B + TILE_M - 1) / TILE_M;
    barriernet_mma_kernel<<<blocks, 256>>>(x, mean_, std_, w1, b1, w21, b21,
                                           w22, b22, w31, b31, w32, b32,
                                           (float2*)d_out, B);
}

// round 10
// speedup vs baseline: 4.2868x; 1.0460x over previous
#include <cuda_runtime.h>
#include <cuda_bf16.h>
#include <cstdint>

// BarrierNet via mma.sync (HMMA) split-precision bf16, sm_80-compatible PTX.
// Layer1 (5->128) as ONE m16n8k16 ([xh|xl]x[wh|wh]) + one m16n8k8 (xh x wl);
// D fragments relu'd/split/repacked in registers as layer2 A fragments.
// Layer2 (128->64) 3-term split bf16 m16n8k16, term-round interleaved for ILP.
// Persistent: 296 blocks loop over 256-row tiles; weights staged once.

__device__ __forceinline__ uint32_t smem_u32(const void* p) {
    uint32_t a;
    asm("{ .reg .u64 t; cvta.to.shared.u64 t, %1; cvt.u32.u64 %0, t; }" : "=r"(a) : "l"(p));
    return a;
}
__device__ __forceinline__ void ldmx4(uint32_t& r0, uint32_t& r1, uint32_t& r2, uint32_t& r3, uint32_t a) {
    asm volatile("ldmatrix.sync.aligned.m8n8.x4.shared.b16 {%0,%1,%2,%3}, [%4];"
                 : "=r"(r0), "=r"(r1), "=r"(r2), "=r"(r3) : "r"(a));
}
__device__ __forceinline__ void ldmx2(uint32_t& r0, uint32_t& r1, uint32_t a) {
    asm volatile("ldmatrix.sync.aligned.m8n8.x2.shared.b16 {%0,%1}, [%2];"
                 : "=r"(r0), "=r"(r1) : "r"(a));
}
__device__ __forceinline__ void mma16(float* c, const uint32_t* a, const uint32_t* b) {
    asm volatile("mma.sync.aligned.m16n8k16.row.col.f32.bf16.bf16.f32 "
                 "{%0,%1,%2,%3}, {%4,%5,%6,%7}, {%8,%9}, {%0,%1,%2,%3};"
                 : "+f"(c[0]), "+f"(c[1]), "+f"(c[2]), "+f"(c[3])
                 : "r"(a[0]), "r"(a[1]), "r"(a[2]), "r"(a[3]), "r"(b[0]), "r"(b[1]));
}
__device__ __forceinline__ void mma8(float* c, const uint32_t* a, uint32_t b) {
    asm volatile("mma.sync.aligned.m16n8k8.row.col.f32.bf16.bf16.f32 "
                 "{%0,%1,%2,%3}, {%4,%5}, {%6}, {%0,%1,%2,%3};"
                 : "+f"(c[0]), "+f"(c[1]), "+f"(c[2]), "+f"(c[3])
                 : "r"(a[0]), "r"(a[1]), "r"(b));
}
// pack two f32 -> bf16x2: first asm operand -> HIGH half
__device__ __forceinline__ uint32_t cvt2(float hi, float lo) {
    uint32_t r;
    asm("cvt.rn.bf16x2.f32 %0, %1, %2;" : "=r"(r) : "f"(hi), "f"(lo));
    return r;
}
__device__ __forceinline__ float lo_f(uint32_t p) { return __uint_as_float(p << 16); }
__device__ __forceinline__ float hi_f(uint32_t p) { return __uint_as_float(p & 0xFFFF0000u); }

static constexpr int TILE_M = 256;

__global__ __launch_bounds__(256, 2) void barriernet_mma_kernel(
    const float* __restrict__ x,
    const float* __restrict__ mean_, const float* __restrict__ std_,
    const float* __restrict__ w1,  const float* __restrict__ b1,
    const float* __restrict__ w21, const float* __restrict__ b21,
    const float* __restrict__ w22, const float* __restrict__ b22,
    const float* __restrict__ w31, const float* __restrict__ b31,
    const float* __restrict__ w32, const float* __restrict__ b32,
    float2* __restrict__ out, int B, int numTiles)
{
    __shared__ __align__(16) float s_x[256][8];       // 8KB: x0..x4, 1, 0, 0
    __shared__ __align__(16) uint4 s_w1h[128], s_w1l[128];   // [n][k8] bf16x2x4
    __shared__ __align__(16) uint4 s_w2h[64][16], s_w2l[64][16]; // [n][chunk] swizzled
    __shared__ __align__(16) float4 s_ep[64];         // (b2, w3row0, w3row1, 0)
    __shared__ float s_b3[4], s_ms[8];

    const int t = threadIdx.x;

    // ---- stage weights ONCE per block ----
    if (t < 128) {
        float v[8];
#pragma unroll
        for (int i = 0; i < 5; i++) v[i] = w1[t * 5 + i];
        v[5] = b1[t]; v[6] = 0.f; v[7] = 0.f;
        uint4 h, l;
        h.x = cvt2(v[1], v[0]); l.x = cvt2(v[1] - hi_f(h.x), v[0] - lo_f(h.x));
        h.y = cvt2(v[3], v[2]); l.y = cvt2(v[3] - hi_f(h.y), v[2] - lo_f(h.y));
        h.z = cvt2(v[5], v[4]); l.z = cvt2(v[5] - hi_f(h.z), v[4] - lo_f(h.z));
        h.w = 0u;               l.w = 0u;
        s_w1h[t] = h; s_w1l[t] = l;
    }
    for (int i = t; i < 64 * 16; i += 256) {
        const int n = i >> 4, c = i & 15;
        const float* src = (n < 32) ? (w21 + n * 128 + c * 8)
                                    : (w22 + (n - 32) * 128 + c * 8);
        uint4 h, l;
        h.x = cvt2(src[1], src[0]); l.x = cvt2(src[1] - hi_f(h.x), src[0] - lo_f(h.x));
        h.y = cvt2(src[3], src[2]); l.y = cvt2(src[3] - hi_f(h.y), src[2] - lo_f(h.y));
        h.z = cvt2(src[5], src[4]); l.z = cvt2(src[5] - hi_f(h.z), src[4] - lo_f(h.z));
        h.w = cvt2(src[7], src[6]); l.w = cvt2(src[7] - hi_f(h.w), src[6] - lo_f(h.w));
        const int cs = c ^ (n & 7);
        s_w2h[n][cs] = h; s_w2l[n][cs] = l;
    }
    if (t < 64) {
        s_ep[t] = (t < 32) ? make_float4(b21[t], w31[t], w31[32 + t], 0.f)
                           : make_float4(b22[t - 32], w32[t - 32], w32[t], 0.f);
    }
    if (t < 4) s_b3[t] = (t < 2) ? b31[t] : b32[t - 2];
    if (t >= 8 && t < 16) s_ms[t - 8] = (t < 12) ? mean_[t - 8] : std_[t - 12];

    const int wid = t >> 5, lane = t & 31;
    const int g = lane >> 2, tig = lane & 3;
    const int rb = wid * 32;
    const uint32_t w1h_base = smem_u32(s_w1h), w1l_base = smem_u32(s_w1l);
    const uint32_t w2h_base = smem_u32(s_w2h), w2l_base = smem_u32(s_w2l);
    const uint32_t nrow  = (uint32_t)((lane & 7) + ((lane & 16) >> 1));
    const uint32_t klane = (uint32_t)((lane >> 3) & 1);
    const int rl = rb + (tig >> 1) * 16 + (tig & 1) * 8 + g;

    for (int tile = blockIdx.x; tile < numTiles; tile += gridDim.x) {
        const int tbase = tile * TILE_M;
        __syncthreads();   // previous tile fully consumed s_x
        // ---- stage x (padded, bias column at k=5) ----
        for (int i = t; i < 256 * 8; i += 256) {
            const int r = i >> 3, k = i & 7;
            float v;
            if (k < 5) { const int gr = min(tbase + r, B - 1); v = x[(size_t)gr * 5 + k]; }
            else v = (k == 5) ? 1.0f : 0.0f;
            s_x[r][k] = v;
        }
        __syncthreads();

        // ---- x fragments (rows g/g+8 per s-slice, k=tig*2,+1) ----
        uint32_t xh[2][2], xl[2][2];
#pragma unroll
        for (int s = 0; s < 2; s++) {
            const float2 v0 = *(const float2*)&s_x[rb + s * 16 + g][tig * 2];
            const float2 v1 = *(const float2*)&s_x[rb + s * 16 + g + 8][tig * 2];
            xh[s][0] = cvt2(v0.y, v0.x);
            xl[s][0] = cvt2(v0.y - hi_f(xh[s][0]), v0.x - lo_f(xh[s][0]));
            xh[s][1] = cvt2(v1.y, v1.x);
            xl[s][1] = cvt2(v1.y - hi_f(xh[s][1]), v1.x - lo_f(xh[s][1]));
        }

        float acc[2][8][4];
#pragma unroll
        for (int s = 0; s < 2; s++)
#pragma unroll
            for (int nf = 0; nf < 8; nf++)
#pragma unroll
                for (int q = 0; q < 4; q++) acc[s][nf][q] = 0.f;

#pragma unroll
        for (int j = 0; j < 8; j++) {
            // ---- layer 1 chunk j: h[rows][16j..16j+15] ----
            uint32_t wh[2], wl[2];
            {
                const uint32_t a = (uint32_t)((j * 16 + (lane & 15)) * 16);
                ldmx2(wh[0], wh[1], w1h_base + a);
                ldmx2(wl[0], wl[1], w1l_base + a);
            }
            uint32_t Ah[2][4], Al[2][4];
#pragma unroll
            for (int s = 0; s < 2; s++) {
                const uint32_t A2[4] = { xh[s][0], xh[s][1], xl[s][0], xl[s][1] };
                float d[2][4];
#pragma unroll
                for (int nf = 0; nf < 2; nf++) {
                    d[nf][0] = d[nf][1] = d[nf][2] = d[nf][3] = 0.f;
                    const uint32_t B2[2] = { wh[nf], wh[nf] };
                    mma16(d[nf], A2, B2);      // xh*wh + xl*wh in one HMMA
                    mma8(d[nf], xh[s], wl[nf]); // + xh*wl
#pragma unroll
                    for (int q = 0; q < 4; q++) d[nf][q] = fmaxf(d[nf][q], 0.f);
                }
                // D(layer1) -> A(layer2) fragment identity
                Ah[s][0] = cvt2(d[0][1], d[0][0]);
                Al[s][0] = cvt2(d[0][1] - hi_f(Ah[s][0]), d[0][0] - lo_f(Ah[s][0]));
                Ah[s][1] = cvt2(d[0][3], d[0][2]);
                Al[s][1] = cvt2(d[0][3] - hi_f(Ah[s][1]), d[0][2] - lo_f(Ah[s][1]));
                Ah[s][2] = cvt2(d[1][1], d[1][0]);
                Al[s][2] = cvt2(d[1][1] - hi_f(Ah[s][2]), d[1][0] - lo_f(Ah[s][2]));
                Ah[s][3] = cvt2(d[1][3], d[1][2]);
                Al[s][3] = cvt2(d[1][3] - hi_f(Ah[s][3]), d[1][2] - lo_f(Ah[s][3]));
            }

            // ---- layer 2: two halves; loads hoisted, term-rounds interleaved ----
#pragma unroll
            for (int half = 0; half < 2; half++) {
                uint32_t bh[2][2][2], bl[2][2][2];   // [pp][frag][reg]
#pragma unroll
                for (int pp = 0; pp < 2; pp++) {
                    const uint32_t n = nrow + (uint32_t)((half * 2 + pp) * 16);
                    const uint32_t a = (n << 8) + ((((uint32_t)(2 * j) + klane) ^ (n & 7)) << 4);
                    ldmx4(bh[pp][0][0], bh[pp][0][1], bh[pp][1][0], bh[pp][1][1], w2h_base + a);
                    ldmx4(bl[pp][0][0], bl[pp][0][1], bl[pp][1][0], bl[pp][1][1], w2l_base + a);
                }
                // 3 term-rounds of 8 independent MMAs: each acc touched once per round
#pragma unroll
                for (int term = 0; term < 3; term++) {
#pragma unroll
                    for (int pp = 0; pp < 2; pp++)
#pragma unroll
                        for (int f = 0; f < 2; f++)
#pragma unroll
                            for (int s = 0; s < 2; s++) {
                                const int ai = (half * 2 + pp) * 2 + f;
                                const uint32_t* A = (term == 1) ? Al[s] : Ah[s];
                                const uint32_t* Bf = (term == 2) ? bl[pp][f] : bh[pp][f];
                                mma16(acc[s][ai], A, Bf);
                            }
                }
            }
        }

        // ---- epilogue: bias+relu, layer-3 dots, quad reduction, QP ----
        float P[4][4];
#pragma unroll
        for (int s = 0; s < 2; s++)
#pragma unroll
            for (int o = 0; o < 2; o++) {
                float pax = 0.f, pay = 0.f, pbx = 0.f, pby = 0.f;
#pragma unroll
                for (int nf = 0; nf < 8; nf++) {
                    const int n0 = nf * 8 + tig * 2;
                    const float4 e0 = s_ep[n0];
                    const float4 e1 = s_ep[n0 + 1];
                    const float y0 = fmaxf(acc[s][nf][o * 2 + 0] + e0.x, 0.f);
                    const float y1 = fmaxf(acc[s][nf][o * 2 + 1] + e1.x, 0.f);
                    if (nf < 4) {
                        pax = fmaf(y0, e0.y, fmaf(y1, e1.y, pax));
                        pay = fmaf(y0, e0.z, fmaf(y1, e1.z, pay));
                    } else {
                        pbx = fmaf(y0, e0.y, fmaf(y1, e1.y, pbx));
                        pby = fmaf(y0, e0.z, fmaf(y1, e1.z, pby));
                    }
                }
                P[s * 2 + o][0] = pax; P[s * 2 + o][1] = pay;
                P[s * 2 + o][2] = pbx; P[s * 2 + o][3] = pby;
            }
#pragma unroll
        for (int sl = 0; sl < 4; sl++)
#pragma unroll
            for (int c = 0; c < 4; c++) {
                P[sl][c] += __shfl_xor_sync(0xFFFFFFFFu, P[sl][c], 1);
                P[sl][c] += __shfl_xor_sync(0xFFFFFFFFu, P[sl][c], 2);
            }

        float uax, uay, ubx, uby;
        if      (tig == 0) { uax = P[0][0]; uay = P[0][1]; ubx = P[0][2]; uby = P[0][3]; }
        else if (tig == 1) { uax = P[1][0]; uay = P[1][1]; ubx = P[1][2]; uby = P[1][3]; }
        else if (tig == 2) { uax = P[2][0]; uay = P[2][1]; ubx = P[2][2]; uby = P[2][3]; }
        else               { uax = P[3][0]; uay = P[3][1]; ubx = P[3][2]; uby = P[3][3]; }

        const int gr = tbase + rl;
        if (gr < B) {
            const float px = s_x[rl][0] * s_ms[4] + s_ms[0];
            const float py = s_x[rl][1] * s_ms[5] + s_ms[1];
            const float th = s_x[rl][2] * s_ms[6] + s_ms[2];
            const float v  = s_x[rl][3] * s_ms[7] + s_ms[3];
            float s, c;
            sincosf(th, &s, &c);
            const float dx = px - 40.0f, dy = py - 15.0f;
            const float barrier = dx * dx + dy * dy - 36.0f;
            const float bdot = 2.0f * dx * v * c + 2.0f * dy * v * s;
            const float Lf2b = 2.0f * v * v;
            const float g1 = -(-2.0f * dx * v * s + 2.0f * dy * v * c);
            const float g2 = -(2.0f * dx * c + 2.0f * dy * s);

            const float u0x = -(uax + s_b3[0]);
            const float u0y = -(uay + s_b3[1]);
            const float z1 = ubx + s_b3[2];
            const float z2 = uby + s_b3[3];
            const float x32_0 = 4.0f / (1.0f + expf(-z1));
            const float x32_1 = 4.0f / (1.0f + expf(-z2));

            const float hq   = Lf2b + (x32_0 + x32_1) * bdot + x32_0 * x32_1 * barrier;
            const float viol = g1 * u0x + g2 * u0y - hq;
            const float gg   = g1 * g1 + g2 * g2;
            const float lam  = fmaxf(viol, 0.f) / (gg + 1e-12f);

            out[gr] = make_float2(u0x - lam * g1, u0y - lam * g2);
        }
    }
}

extern "C" void kernel_launch(void* const* d_in, const int* in_sizes, int n_in,
                              void* d_out, int out_size) {
    const float* x     = (const float*)d_in[0];
    const float* mean_ = (const float*)d_in[2];
    const float* std_  = (const float*)d_in[3];
    const float* w1    = (const float*)d_in[4];
    const float* b1    = (const float*)d_in[5];
    const float* w21   = (const float*)d_in[6];
    const float* b21   = (const float*)d_in[7];
    const float* w22   = (const float*)d_in[8];
    const float* b22   = (const float*)d_in[9];
    const float* w31   = (const float*)d_in[10];
    const float* b31   = (const float*)d_in[11];
    const float* w32   = (const float*)d_in[12];
    const float* b32   = (const float*)d_in[13];

    const int B = in_sizes[0] / 5;
    const int numTiles = (B + TILE_M - 1) / TILE_M;
    const int blocks = 296;   // 2 CTAs/SM x 148 SMs, persistent over tiles
    barriernet_mma_kernel<<<blocks, 256>>>(x, mean_, std_, w1, b1, w21, b21,
                                           w22, b22, w31, b31, w32, b32,
                                           (float2*)d_out, B, numTiles);
}